// round 4
// baseline (speedup 1.0000x reference)
#include <cuda_runtime.h>

#define N_FWD  8192
#define T_LEN  4096
#define PAD    2048
#define B_MAX  64
#define FROW   4104           // g_F row stride in float2 (4097 rounded up)
#define FTH    1024
#define ITH    256

// Padding schemes
#define PHYS(i)  ((i) + ((i) >> 3))    // radix-8 fwd kernel
#define P16(i)   ((i) + ((i) >> 4))    // radix-16 inv kernel
#define FWD_PAD  9216                  // PHYS(8191)=9214 -> 9216
#define INV_PAD  4352                  // P16(4095)=4350 -> 4352

__device__ float2 g_tw[4096];          // e^{-2 pi i k/8192}, k<4096   (fwd)
__device__ float2 g_rot[4096];         // e^{+2 pi i k/8192}, k<4096   (odd-pass rotation)
__device__ float2 g_tw4k[4096];        // e^{+2 pi i k/4096}, k<4096   (inv stage twiddles)
__device__ float2 g_F[B_MAX * FROW];   // half spectra F[k], k in [0,4096]

// ---------------------------------------------------------------------------
__global__ void twiddle_init_kernel() {
    int k = blockIdx.x * blockDim.x + threadIdx.x;
    if (k < 4096) {
        float s, c;
        sincospif((float)k * (1.0f / 4096.0f), &s, &c);
        g_tw[k]  = make_float2(c, -s);
        g_rot[k] = make_float2(c,  s);
        float s2, c2;
        sincospif((float)k * (1.0f / 2048.0f), &s2, &c2);
        g_tw4k[k] = make_float2(c2, s2);
    }
}

__device__ __forceinline__ void cmul(float& zr, float& zi,
                                     float ar, float ai, float br, float bi) {
    zr = ar * br - ai * bi;
    zi = ar * bi + ai * br;
}

// ===========================================================================
// FORWARD 8192-pt FFT (radix-8, unchanged structure from prev round)
// ===========================================================================
template<bool FWD>
__device__ __forceinline__ void bfly8(float* xr, float* xi)
{
    const float C = 0.70710678118654752440f;
    float t0r=xr[0]+xr[4], t0i=xi[0]+xi[4];
    float t4r=xr[0]-xr[4], t4i=xi[0]-xi[4];
    float t1r=xr[1]+xr[5], t1i=xi[1]+xi[5];
    float t5r=xr[1]-xr[5], t5i=xi[1]-xi[5];
    float t2r=xr[2]+xr[6], t2i=xi[2]+xi[6];
    float t6r=xr[2]-xr[6], t6i=xi[2]-xi[6];
    float t3r=xr[3]+xr[7], t3i=xi[3]+xi[7];
    float t7r=xr[3]-xr[7], t7i=xi[3]-xi[7];

    float u0r=t0r+t2r, u0i=t0i+t2i;
    float u1r=t0r-t2r, u1i=t0i-t2i;
    float u2r=t1r+t3r, u2i=t1i+t3i;
    float u3r=t1r-t3r, u3i=t1i-t3i;
    xr[0]=u0r+u2r; xi[0]=u0i+u2i;
    xr[4]=u0r-u2r; xi[4]=u0i-u2i;
    if (FWD) { xr[2]=u1r+u3i; xi[2]=u1i-u3r; xr[6]=u1r-u3i; xi[6]=u1i+u3r; }
    else     { xr[2]=u1r-u3i; xi[2]=u1i+u3r; xr[6]=u1r+u3i; xi[6]=u1i-u3r; }

    float a5r,a5i,a6r,a6i,a7r,a7i;
    if (FWD) {
        a5r =  C*(t5r+t5i);  a5i =  C*(t5i-t5r);
        a6r =  t6i;          a6i = -t6r;
        a7r =  C*(t7i-t7r);  a7i = -C*(t7r+t7i);
    } else {
        a5r =  C*(t5r-t5i);  a5i =  C*(t5r+t5i);
        a6r = -t6i;          a6i =  t6r;
        a7r = -C*(t7r+t7i);  a7i =  C*(t7r-t7i);
    }
    float v0r=t4r+a6r, v0i=t4i+a6i;
    float v1r=t4r-a6r, v1i=t4i-a6i;
    float v2r=a5r+a7r, v2i=a5i+a7i;
    float v3r=a5r-a7r, v3i=a5i-a7i;
    xr[1]=v0r+v2r; xi[1]=v0i+v2i;
    xr[5]=v0r-v2r; xi[5]=v0i-v2i;
    if (FWD) { xr[3]=v1r+v3i; xi[3]=v1i-v3r; xr[7]=v1r-v3i; xi[7]=v1i+v3r; }
    else     { xr[3]=v1r-v3i; xi[3]=v1i+v3r; xr[7]=v1r+v3i; xi[7]=v1i-v3r; }
}

__device__ __forceinline__ void store8(float* dr, float* di,
                                       const float* xr, const float* xi,
                                       int o, int m, float w1r, float w1i)
{
    float cr = 1.0f, ci = 0.0f;
    #pragma unroll
    for (int r = 0; r < 8; ++r) {
        int p = PHYS(o + r * m);
        dr[p] = xr[r] * cr - xi[r] * ci;
        di[p] = xr[r] * ci + xi[r] * cr;
        float nr = cr * w1r - ci * w1i;
        ci = cr * w1i + ci * w1r;
        cr = nr;
    }
}

__device__ __forceinline__ void fwd_stage(const float* sr, const float* si,
                                          float* dr, float* di, int m, int tid)
{
    float xr[8], xi[8];
    #pragma unroll
    for (int q = 0; q < 8; ++q) {
        int p = PHYS(tid + q * 1024);
        xr[q] = sr[p]; xi[q] = si[p];
    }
    bfly8<true>(xr, xi);
    int k = tid & (m - 1), jm = tid - k;
    float2 t = g_tw[jm];
    store8(dr, di, xr, xi, 8 * jm + k, m, t.x, t.y);
}

extern __shared__ float sm_[];

__global__ void __launch_bounds__(FTH, 1)
fwd_fft_kernel(const float* __restrict__ in)
{
    float* Ar = sm_;
    float* Ai = sm_ + FWD_PAD;
    float* Br = sm_ + 2 * FWD_PAD;
    float* Bi = sm_ + 3 * FWD_PAD;

    const int b = blockIdx.x, tid = threadIdx.x;
    const float* x = in + b * T_LEN;

    {
        float xr[8], xi[8];
        #pragma unroll
        for (int q = 0; q < 8; ++q) {
            int i = tid + q * 1024;
            int src;
            if (i < PAD)              src = PAD - 1 - i;
            else if (i < PAD + T_LEN) src = i - PAD;
            else                      src = (2 * T_LEN + PAD - 1) - i;
            xr[q] = x[src]; xi[q] = 0.0f;
        }
        bfly8<true>(xr, xi);
        float2 t = g_tw[tid];
        store8(Ar, Ai, xr, xi, 8 * tid, 1, t.x, t.y);
    }
    __syncthreads();
    fwd_stage(Ar, Ai, Br, Bi,   8, tid); __syncthreads();
    fwd_stage(Br, Bi, Ar, Ai,  64, tid); __syncthreads();
    fwd_stage(Ar, Ai, Br, Bi, 512, tid); __syncthreads();

    float2* Fo = g_F + b * FROW;
    #pragma unroll
    for (int q = 0; q < 4; ++q) {
        int k = tid + q * 1024;
        float ur = Br[PHYS(k)],        ui = Bi[PHYS(k)];
        float vr = Br[PHYS(k + 4096)], vi = Bi[PHYS(k + 4096)];
        Fo[k] = make_float2(ur + vr, ui + vi);
        if (k == 0) Fo[4096] = make_float2(ur - vr, ui - vi);
    }
}

// ===========================================================================
// INVERSE: radix-16 Stockham, 4096 = 16^3, 256 threads, in-place smem.
// ===========================================================================

// step1: four in-place inverse radix-4s over stride-4 groups.
// After this, y[b][r1] lives at slot b + 4*r1.
__device__ __forceinline__ void bfly16_step1(float* xr, float* xi)
{
    #pragma unroll
    for (int b = 0; b < 4; ++b) {
        float p0r=xr[b],    p0i=xi[b];
        float p1r=xr[b+4],  p1i=xi[b+4];
        float p2r=xr[b+8],  p2i=xi[b+8];
        float p3r=xr[b+12], p3i=xi[b+12];
        float u0r=p0r+p2r, u0i=p0i+p2i;
        float u1r=p0r-p2r, u1i=p0i-p2i;
        float u2r=p1r+p3r, u2i=p1i+p3i;
        float u3r=p1r-p3r, u3i=p1i-p3i;
        xr[b]    = u0r+u2r; xi[b]    = u0i+u2i;
        xr[b+4]  = u1r-u3i; xi[b+4]  = u1i+u3r;   // * (+i)
        xr[b+8]  = u0r-u2r; xi[b+8]  = u0i-u2i;
        xr[b+12] = u1r+u3i; xi[b+12] = u1i-u3r;   // * (-i)
    }
}

#define C_SQ 0.70710678118654752440f
#define C_8  0.92387953251128675613f
#define S_8  0.38268343236508977173f

// step2 (intra-16 twiddles e^{+i pi b r1/8}) + step3 radix-4 over b +
// stage output twiddle W^r (from g_tw4k[jm*r]) + padded STS.
__device__ __forceinline__ void bfly16_finish_store(
    const float* xr, const float* xi, float* Sr, float* Si,
    int o, int m, int jm)
{
    const float Tr[4][4] = {{1,1,1,1},
                            {1, C_8,  C_SQ,  S_8},
                            {1, C_SQ, 0.0f, -C_SQ},
                            {1, S_8, -C_SQ, -C_8}};
    const float Ti[4][4] = {{0,0,0,0},
                            {0, S_8,  C_SQ,  C_8},
                            {0, C_SQ, 1.0f,  C_SQ},
                            {0, C_8,  C_SQ, -S_8}};
    #pragma unroll
    for (int r1 = 0; r1 < 4; ++r1) {
        float zr[4], zi[4];
        #pragma unroll
        for (int b = 0; b < 4; ++b) {
            int sl = 4 * r1 + b;
            cmul(zr[b], zi[b], xr[sl], xi[sl], Tr[b][r1], Ti[b][r1]);
        }
        float u0r=zr[0]+zr[2], u0i=zi[0]+zi[2];
        float u1r=zr[0]-zr[2], u1i=zi[0]-zi[2];
        float u2r=zr[1]+zr[3], u2i=zi[1]+zi[3];
        float u3r=zr[1]-zr[3], u3i=zi[1]-zi[3];
        float Yr[4], Yi[4];
        Yr[0]=u0r+u2r; Yi[0]=u0i+u2i;
        Yr[1]=u1r-u3i; Yi[1]=u1i+u3r;
        Yr[2]=u0r-u2r; Yi[2]=u0i-u2i;
        Yr[3]=u1r+u3i; Yi[3]=u1i-u3r;
        #pragma unroll
        for (int r2 = 0; r2 < 4; ++r2) {
            int r = r1 + 4 * r2;
            float2 W = g_tw4k[jm * r];           // e^{+2 pi i jm r/4096}
            float wr, wi;
            cmul(wr, wi, Yr[r2], Yi[r2], W.x, W.y);
            int p = P16(o + r * m);
            Sr[p] = wr; Si[p] = wi;
        }
    }
}

__global__ void __launch_bounds__(ITH, 3)
cwt_kernel(const float* __restrict__ wft, float* __restrict__ out, int S)
{
    float* Xr = sm_;
    float* Xi = sm_ + INV_PAD;

    const int tid = threadIdx.x;
    const int s = blockIdx.x % S, b = blockIdx.x / S;
    const float2* __restrict__ F = g_F + b * FROW;
    const float*  __restrict__ w = wft + (size_t)s * N_FWD;
    const float inv_n = 1.0f / 8192.0f;

    float2 fn = F[4096];
    float  gn = w[4096] * inv_n;
    float  nyr = fn.x * gn, nyi = fn.y * gn;

    float ev[8];                         // pass-0 log values (same thread/indices)

    const float Tr[4][4] = {{1,1,1,1},
                            {1, C_8,  C_SQ,  S_8},
                            {1, C_SQ, 0.0f, -C_SQ},
                            {1, S_8, -C_SQ, -C_8}};
    const float Ti[4][4] = {{0,0,0,0},
                            {0, S_8,  C_SQ,  C_8},
                            {0, C_SQ, 1.0f,  C_SQ},
                            {0, C_8,  C_SQ, -S_8}};

    #pragma unroll
    for (int pass = 0; pass < 2; ++pass) {
        float xr[16], xi[16];

        // ---- stage 1 (m=1, jm=tid): fused global load + spectrum multiply
        #pragma unroll
        for (int q = 0; q < 16; ++q) {
            int k = tid + 256 * q;
            float2 f = F[k];
            float  g = w[k] * inv_n;
            float vr = f.x * g, vi = f.y * g;
            if (pass) {                          // * e^{+2 pi i k/8192}
                float2 c = g_rot[k];
                float r2 = vr * c.x - vi * c.y;
                float i2 = vi * c.x + vr * c.y;
                vr = r2; vi = i2;
            }
            xr[q] = vr; xi[q] = vi;
        }
        bfly16_step1(xr, xi);
        bfly16_finish_store(xr, xi, Xr, Xi, 16 * tid, 1, tid);
        __syncthreads();

        // ---- stage 2 (m=16)
        #pragma unroll
        for (int q = 0; q < 16; ++q) {
            int p = P16(tid + 256 * q);
            xr[q] = Xr[p]; xi[q] = Xi[p];
        }
        bfly16_step1(xr, xi);                    // register-only, pre-barrier
        __syncthreads();                         // all reads done -> safe to overwrite
        {
            int k2 = tid & 15, jm2 = tid - k2;
            bfly16_finish_store(xr, xi, Xr, Xi, 16 * jm2 + k2, 16, jm2);
        }
        __syncthreads();

        // ---- stage 3 (m=256, jm=0, W=1): fused Nyquist + log|.| + output
        #pragma unroll
        for (int q = 0; q < 16; ++q) {
            int p = P16(tid + 256 * q);
            xr[q] = Xr[p]; xi[q] = Xi[p];
        }
        bfly16_step1(xr, xi);

        float nr = pass ? -nyr : nyr;
        float ni = pass ? -nyi : nyi;
        float2* o2 = (float2*)(out + (size_t)blockIdx.x * T_LEN);

        #pragma unroll
        for (int r1 = 0; r1 < 4; ++r1) {
            float zr[4], zi[4];
            #pragma unroll
            for (int bb = 0; bb < 4; ++bb) {
                int sl = 4 * r1 + bb;
                cmul(zr[bb], zi[bb], xr[sl], xi[sl], Tr[bb][r1], Ti[bb][r1]);
            }
            float u0r=zr[0]+zr[2], u0i=zi[0]+zi[2];
            float u1r=zr[0]-zr[2], u1i=zi[0]-zi[2];
            float u2r=zr[1]+zr[3], u2i=zi[1]+zi[3];
            float u3r=zr[1]-zr[3], u3i=zi[1]-zi[3];

            // r = r1+4 (u in [1024,2048)) -> out col c1 = tid + 256*r1
            float y1r = u1r - u3i + nr, y1i = u1i + u3r + ni;
            float l1 = 0.5f * __logf(y1r * y1r + y1i * y1i);
            // r = r1+8 (u in [2048,3072)) -> out col c1 + 1024
            float y2r = u0r - u2r + nr, y2i = u0i - u2i + ni;
            float l2 = 0.5f * __logf(y2r * y2r + y2i * y2i);

            if (pass == 0) {
                ev[r1]     = l1;
                ev[4 + r1] = l2;
            } else {
                int c1 = tid + 256 * r1;
                o2[c1]        = make_float2(ev[r1],     l1);
                o2[c1 + 1024] = make_float2(ev[4 + r1], l2);
            }
        }
        __syncthreads();                         // before next pass overwrites smem
    }
}

// ---------------------------------------------------------------------------
extern "C" void kernel_launch(void* const* d_in, const int* in_sizes, int n_in,
                              void* d_out, int out_size)
{
    const float* in  = (const float*)d_in[0];
    const float* wft = (const float*)d_in[1];
    float* out = (float*)d_out;

    const int B = in_sizes[0] / T_LEN;     // 64
    const int S = in_sizes[1] / N_FWD;     // 75

    const int fwd_smem = 4 * FWD_PAD * sizeof(float);   // 147456 B
    const int cwt_smem = 2 * INV_PAD * sizeof(float);   //  34816 B
    cudaFuncSetAttribute(fwd_fft_kernel,
                         cudaFuncAttributeMaxDynamicSharedMemorySize, fwd_smem);
    cudaFuncSetAttribute(cwt_kernel,
                         cudaFuncAttributeMaxDynamicSharedMemorySize, cwt_smem);

    twiddle_init_kernel<<<16, 256>>>();
    fwd_fft_kernel<<<B, FTH, fwd_smem>>>(in);
    cwt_kernel<<<B * S, ITH, cwt_smem>>>(wft, out, S);
}